// round 13
// baseline (speedup 1.0000x reference)
#include <cuda_runtime.h>
#include <math.h>

#define NP 4096
#define NS 128
#define CH 256
#define PPOOL (NP * NS)   // elements per pool (float32 reals)

typedef unsigned long long u64;

// ---- packed f32x2 helpers (Blackwell-only FFMA2 path, PTX-reachable only) ----
__device__ __forceinline__ u64 pk(float lo, float hi)
{ u64 r; asm("mov.b64 %0,{%1,%2};" : "=l"(r) : "f"(lo), "f"(hi)); return r; }
__device__ __forceinline__ float lo32(u64 v)
{ float a, b; asm("mov.b64 {%0,%1},%2;" : "=f"(a), "=f"(b) : "l"(v)); return a; }
__device__ __forceinline__ u64 swp(u64 v)
{ unsigned a, b; asm("mov.b64 {%0,%1},%2;" : "=r"(a), "=r"(b) : "l"(v));
  u64 r; asm("mov.b64 %0,{%1,%2};" : "=l"(r) : "r"(b), "r"(a)); return r; }
__device__ __forceinline__ u64 fma2(u64 a, u64 b, u64 c)
{ u64 d; asm("fma.rn.f32x2 %0,%1,%2,%3;" : "=l"(d) : "l"(a), "l"(b), "l"(c)); return d; }
__device__ __forceinline__ u64 mul2(u64 a, u64 b)
{ u64 d; asm("mul.rn.f32x2 %0,%1,%2;" : "=l"(d) : "l"(a), "l"(b)); return d; }

// Zero-fill for pools 3,4 (Fp_b, Fm_b identically zero).
__global__ void epg_zero1(float* __restrict__ p, int n)
{
    int k = blockIdx.x * blockDim.x + threadIdx.x;
    if (k < n) p[k] = 0.f;
}

__global__ void __launch_bounds__(128, 1)
epg_mt_kernel(const float* __restrict__ flip, const float* __restrict__ phase,
              const float* __restrict__ pT1f, const float* __restrict__ pT2f,
              const float* __restrict__ pT1b, const float* __restrict__ pT2b,
              const float* __restrict__ pkf,  const float* __restrict__ pkb,
              const float* __restrict__ pTR,  const float* __restrict__ pB0,
              const float* __restrict__ pB1,  const float* __restrict__ pwf,
              const float* __restrict__ pwb,
              float* __restrict__ out)
{
    // Packed per-pulse constants, 13 u64 forms in 7 ulonglong2 slots:
    // slot0={P1d,P1n} slot1={P1n2,P2a} slot2={P2b,P2b2} slot3={Cd,Cn}
    // slot4={Cn2,Qd}  slot5={Qn,Qn2}  slot6={CK,pad}
    __shared__ ulonglong2 sK[CH + 1][7];
    __shared__ u64 shFp[2][NS];
    __shared__ u64 shFm[2][NS];

    const int i = threadIdx.x;                 // state 0..127

    // ---- scalar params / derived constants ----
    const float TR  = pTR[0];
    const float T1f = pT1f[0], T2f = pT2f[0];
    const float T1b = pT1b[0];
    const float kf  = pkf[0],  kb  = pkb[0];
    const float B0  = pB0[0],  B1  = pB1[0];
    const float wf  = pwf[0],  wb  = pwb[0];

    const float E1f = expf(-TR / T1f);
    const float E2f = expf(-TR / T2f);
    const float E1b = expf(-TR / T1b);
    const float scale = TR / 1000.0f;

    const float a1 = E1f - kf * scale;
    const float a2 = kb * scale;
    const float Cf = (1.0f - E1f) * wf;
    const float b1 = E1b - kb * scale;
    const float b2 = kf * scale;
    const float Cb = (1.0f - E1b) * wb;

    const float phi = 2.0f * 3.14159265358979323846f * B0 * TR / 1000.0f;
    float rs, rc;
    sincosf(phi, &rs, &rc);
    const float Rx = E2f * rc;     // R = E2f * e^{i phi}
    const float Ry = E2f * rs;

    // Loop-invariant packed constants for the Z recurrence
    const u64 A1  = pk(a1, a1), A2  = pk(a2, a2), CF0 = pk(Cf, 0.f);
    const u64 B1p = pk(b1, b1), B2p = pk(b2, b2), CB0 = pk(Cb, 0.f);

    // ---- initial carry (packed complex) ----
    u64 Fp = 0ull, Fm = 0ull;
    u64 Zf = (i == 0) ? pk(wf, 0.f) : 0ull;
    u64 Zb = (i == 0) ? pk(wb, 0.f) : 0ull;

    const bool is0   = (i == 0);
    const bool is127 = (i == NS - 1);
    const int  iprev = (i + NS - 1) & (NS - 1);
    const int  inext = (i + 1) & (NS - 1);

    // Rotated-column output pointers (post-shift layout, stores off-chain).
    float* p0 = out + inext;
    float* p1 = out + PPOOL + iprev;
    float* p2 = out + 2 * PPOOL + i;
    float* p5 = out + 5 * PPOOL + i;

    int b = 0;

    for (int base = 0; base < NP; base += CH) {
        __syncthreads();   // previous chunk's const readers done
        // ---- cooperative precompute of packed per-pulse constants ----
        for (int j = i; j < CH; j += 128) {
            float fa = flip[base + j] * B1;
            float ph = phase[base + j];
            float s, c;
            sincosf(0.5f * fa, &s, &c);
            float c2 = c * c, s2 = s * s, cs = c * s;
            float sb, cb;
            sincosf(ph, &sb, &cb);
            float Ax = s2 * (cb * cb - sb * sb);
            float Ay = s2 * (2.f * sb * cb);
            float Cx = -cs * sb;
            float Cy =  cs * cb;
            float P1x = c2 * Rx,            P1y = c2 * Ry;
            float P2x = Ax * Rx - Ay * Ry,  P2y = Ax * Ry + Ay * Rx;
            float Qx  = Cx * Rx + Cy * Ry,  Qy  = Cx * Ry - Cy * Rx;
            float ck  = c2 - s2;
            sK[j][0] = make_ulonglong2(pk(P1x,  P1x), pk(-P1y, P1y));
            sK[j][1] = make_ulonglong2(pk(P1y, -P1y), pk(P2x, -P2x));
            sK[j][2] = make_ulonglong2(pk(P2y,  P2y), pk(-P2y, -P2y));
            sK[j][3] = make_ulonglong2(pk(Cx,   Cx),  pk(-Cy,  Cy));
            sK[j][4] = make_ulonglong2(pk(Cy,  -Cy),  pk(Qx,   Qx));
            sK[j][5] = make_ulonglong2(pk(-Qy,  Qy),  pk(Qy,  -Qy));
            sK[j][6] = make_ulonglong2(pk(ck,   ck),  0ull);
        }
        __syncthreads();

        ulonglong2 q0 = sK[0][0], q1 = sK[0][1], q2 = sK[0][2], q3 = sK[0][3],
                   q4 = sK[0][4], q5 = sK[0][5], q6 = sK[0][6];

        #pragma unroll 2
        for (int t = 0; t < CH; ++t) {
            const u64 P1d = q0.x, P1n = q0.y, P1n2 = q1.x, P2a = q1.y;
            const u64 P2b = q2.x, P2b2 = q2.y, Cd = q3.x, Cn = q3.y;
            const u64 Cn2 = q4.x, Qd = q4.y, Qn = q5.x, Qn2 = q5.y;
            const u64 CK  = q6.x;

            // --- T1 relaxation + exchange (packed) ---
            u64 zf = fma2(A2,  Zb, fma2(A1,  Zf, CF0));
            u64 zb = fma2(B2p, Zf, fma2(B1p, Zb, CB0));

            u64 FpS = swp(Fp), FmS = swp(Fm), zfS = swp(zf);

            // Fpn = P1*Fp + P2*conj(Fm) + C*zf
            u64 t1 = fma2(Cn, zfS, mul2(Cd, zf));
            t1 = fma2(P2b, FmS, fma2(P2a, Fm, t1));
            u64 Fpn = fma2(P1n, FpS, fma2(P1d, Fp, t1));
            // Fmn = conj(P2)*conj(Fp) + conj(P1)*Fm + conj(C)*zf
            u64 t2 = fma2(Cn2, zfS, mul2(Cd, zf));
            t2 = fma2(P2b2, FpS, fma2(P2a, Fp, t2));
            u64 Fmn = fma2(P1n2, FmS, fma2(P1d, Fm, t2));
            // Zfn = Q1*Fp + conj(Q1)*Fm + ck*zf
            u64 t3 = fma2(Qn, FpS, mul2(Qd, Fp));
            t3 = fma2(Qn2, FmS, fma2(Qd, Fm, t3));
            u64 Zfn = fma2(CK, zf, t3);

            // --- global stores (real parts, rotated columns = post-shift) ---
            p0[0] = is127 ? 0.f : lo32(Fpn);
            p1[0] = is0   ? 0.f : lo32(Fmn);
            p2[0] = lo32(Zfn);
            p5[0] = lo32(zb);
            p0 += NS; p1 += NS; p2 += NS; p5 += NS;

            // --- exchange for +-1 gradient shift ---
            shFp[b][i] = Fpn;
            shFm[b][i] = Fmn;
            // prefetch next pulse's constants BEFORE the barrier (chunk-stable
            // shared region -> safe; LDS latency hides under BAR wait)
            q0 = sK[t + 1][0]; q1 = sK[t + 1][1]; q2 = sK[t + 1][2];
            q3 = sK[t + 1][3]; q4 = sK[t + 1][4]; q5 = sK[t + 1][5];
            q6 = sK[t + 1][6];
            __syncthreads();
            u64 pv = shFp[b][iprev];
            u64 mv = shFm[b][inext];
            Fp = is0   ? 0ull : pv;
            Fm = is127 ? 0ull : mv;
            Zf = Zfn;
            Zb = zb;
            b ^= 1;
        }
    }
}

extern "C" void kernel_launch(void* const* d_in, const int* in_sizes, int n_in,
                              void* d_out, int out_size)
{
    (void)in_sizes; (void)n_in;
    const float* flip  = (const float*)d_in[0];
    const float* phase = (const float*)d_in[1];
    const float* T1f   = (const float*)d_in[2];
    const float* T2f   = (const float*)d_in[3];
    const float* T1b   = (const float*)d_in[4];
    const float* T2b   = (const float*)d_in[5];
    const float* kf    = (const float*)d_in[6];
    const float* kb    = (const float*)d_in[7];
    const float* TR    = (const float*)d_in[8];
    // d_in[9] = TE (unused by the reference math)
    const float* B0    = (const float*)d_in[10];
    const float* B1    = (const float*)d_in[11];
    const float* wf    = (const float*)d_in[12];
    const float* wb    = (const float*)d_in[13];

    // Zero-fill pools 3,4 (identically zero), clamped to buffer size.
    long long z_lo = (long long)3 * PPOOL;
    long long z_hi = (long long)5 * PPOOL;
    if (z_hi > (long long)out_size) z_hi = out_size;
    if (z_hi > z_lo) {
        int n = (int)(z_hi - z_lo);
        epg_zero1<<<(n + 255) / 256, 256>>>((float*)d_out + z_lo, n);
    }

    epg_mt_kernel<<<1, 128>>>(flip, phase, T1f, T2f, T1b, T2b, kf, kb,
                              TR, B0, B1, wf, wb, (float*)d_out);
}

// round 14
// speedup vs baseline: 1.0620x; 1.0620x over previous
#include <cuda_runtime.h>
#include <math.h>

#define NP 4096
#define NS 128
#define CH 256
#define PPOOL (NP * NS)   // elements per pool (float32 reals)

typedef unsigned long long u64;

// ---- packed f32x2 helpers (FFMA2 reachable only via PTX) ----
__device__ __forceinline__ u64 pk(float lo, float hi)
{ u64 r; asm("mov.b64 %0,{%1,%2};" : "=l"(r) : "f"(lo), "f"(hi)); return r; }
__device__ __forceinline__ float lo32(u64 v)
{ float a, b; asm("mov.b64 {%0,%1},%2;" : "=f"(a), "=f"(b) : "l"(v)); return a; }
__device__ __forceinline__ u64 swp(u64 v)
{ unsigned a, b; asm("mov.b64 {%0,%1},%2;" : "=r"(a), "=r"(b) : "l"(v));
  u64 r; asm("mov.b64 %0,{%1,%2};" : "=l"(r) : "r"(b), "r"(a)); return r; }
__device__ __forceinline__ u64 fma2(u64 a, u64 b, u64 c)
{ u64 d; asm("fma.rn.f32x2 %0,%1,%2,%3;" : "=l"(d) : "l"(a), "l"(b), "l"(c)); return d; }
__device__ __forceinline__ u64 mul2(u64 a, u64 b)
{ u64 d; asm("mul.rn.f32x2 %0,%1,%2;" : "=l"(d) : "l"(a), "l"(b)); return d; }
__device__ __forceinline__ u64 add2(u64 a, u64 b)
{ u64 d; asm("add.rn.f32x2 %0,%1,%2;" : "=l"(d) : "l"(a), "l"(b)); return d; }

// Zero-fill for pools 3,4 (Fp_b, Fm_b identically zero).
__global__ void epg_zero1(float* __restrict__ p, int n)
{
    int k = blockIdx.x * blockDim.x + threadIdx.x;
    if (k < n) p[k] = 0.f;
}

__global__ void __launch_bounds__(128, 1)
epg_mt_kernel(const float* __restrict__ flip, const float* __restrict__ phase,
              const float* __restrict__ pT1f, const float* __restrict__ pT2f,
              const float* __restrict__ pT1b, const float* __restrict__ pT2b,
              const float* __restrict__ pkf,  const float* __restrict__ pkb,
              const float* __restrict__ pTR,  const float* __restrict__ pB0,
              const float* __restrict__ pB1,  const float* __restrict__ pwf,
              const float* __restrict__ pwb,
              float* __restrict__ out)
{
    // Packed per-pulse constants, 13 u64 forms in 7 ulonglong2 slots:
    // [0]={P1d,P1n} [1]={P1n2,P2a} [2]={P2b,P2b2} [3]={Cd,Cn}
    // [4]={Cn2,Qd}  [5]={Qn,Qn2}   [6]={CK,0}
    __shared__ ulonglong2 sK[CH][7];
    // Exchange buffers with PERMANENT zero halos:
    //   exFp[b][0]  == 0 : thread i writes slot i+1, reads slot i
    //   exFm[b][NS] == 0 : thread i writes slot i,   reads slot i+1
    __shared__ u64 exFp[2][NS + 1];
    __shared__ u64 exFm[2][NS + 1];

    const int i = threadIdx.x;                 // state 0..127

    // ---- scalar params / derived constants ----
    const float TR  = pTR[0];
    const float T1f = pT1f[0], T2f = pT2f[0];
    const float T1b = pT1b[0];
    const float kf  = pkf[0],  kb  = pkb[0];
    const float B0  = pB0[0],  B1  = pB1[0];
    const float wf  = pwf[0],  wb  = pwb[0];

    const float E1f = expf(-TR / T1f);
    const float E2f = expf(-TR / T2f);
    const float E1b = expf(-TR / T1b);
    const float scale = TR / 1000.0f;

    const float a1 = E1f - kf * scale;
    const float a2 = kb * scale;
    const float Cf = (1.0f - E1f) * wf;
    const float b1 = E1b - kb * scale;
    const float b2 = kf * scale;
    const float Cb = (1.0f - E1b) * wb;

    const float phi = 2.0f * 3.14159265358979323846f * B0 * TR / 1000.0f;
    float rs, rc;
    sincosf(phi, &rs, &rc);
    const float Rx = E2f * rc;     // R = E2f * e^{i phi}
    const float Ry = E2f * rs;

    // Loop-invariant packed constants for the Z recurrence
    const u64 A1  = pk(a1, a1), A2  = pk(a2, a2), CF0 = pk(Cf, 0.f);
    const u64 B1p = pk(b1, b1), B2p = pk(b2, b2), CB0 = pk(Cb, 0.f);

    // ---- initial carry (packed complex) ----
    u64 Fp = 0ull, Fm = 0ull;
    u64 Zf = (i == 0) ? pk(wf, 0.f) : 0ull;
    u64 Zb = (i == 0) ? pk(wb, 0.f) : 0ull;

    const bool is0   = (i == 0);
    const bool is127 = (i == NS - 1);
    const int  iprev = (i + NS - 1) & (NS - 1);
    const int  inext = (i + 1) & (NS - 1);

    // Zero the halo slots ONCE (never overwritten afterwards).
    if (i == 0) {
        exFp[0][0]  = 0ull; exFp[1][0]  = 0ull;
        exFm[0][NS] = 0ull; exFm[1][NS] = 0ull;
    }

    // Rotated-column output pointers (post-shift layout, stores off-chain).
    float* p0 = out + inext;
    float* p1 = out + PPOOL + iprev;
    float* p2 = out + 2 * PPOOL + i;
    float* p5 = out + 5 * PPOOL + i;

    int b = 0;

    for (int base = 0; base < NP; base += CH) {
        __syncthreads();   // previous chunk's const readers done
        // ---- cooperative precompute of packed per-pulse constants ----
        for (int j = i; j < CH; j += 128) {
            float fa = flip[base + j] * B1;
            float ph = phase[base + j];
            float s, c;
            sincosf(0.5f * fa, &s, &c);
            float c2 = c * c, s2 = s * s, cs = c * s;
            float sb, cb;
            sincosf(ph, &sb, &cb);
            float Ax = s2 * (cb * cb - sb * sb);
            float Ay = s2 * (2.f * sb * cb);
            float Cx = -cs * sb;
            float Cy =  cs * cb;
            float P1x = c2 * Rx,            P1y = c2 * Ry;
            float P2x = Ax * Rx - Ay * Ry,  P2y = Ax * Ry + Ay * Rx;
            float Qx  = Cx * Rx + Cy * Ry,  Qy  = Cx * Ry - Cy * Rx;
            float ck  = c2 - s2;
            sK[j][0] = make_ulonglong2(pk(P1x,  P1x), pk(-P1y, P1y));
            sK[j][1] = make_ulonglong2(pk(P1y, -P1y), pk(P2x, -P2x));
            sK[j][2] = make_ulonglong2(pk(P2y,  P2y), pk(-P2y, -P2y));
            sK[j][3] = make_ulonglong2(pk(Cx,   Cx),  pk(-Cy,  Cy));
            sK[j][4] = make_ulonglong2(pk(Cy,  -Cy),  pk(Qx,   Qx));
            sK[j][5] = make_ulonglong2(pk(-Qy,  Qy),  pk(Qy,  -Qy));
            sK[j][6] = make_ulonglong2(pk(ck,   ck),  0ull);
        }
        __syncthreads();

        #pragma unroll 2
        for (int t = 0; t < CH; ++t) {
            // Direct broadcast loads (no register-copy pipeline; ptxas hoists).
            const ulonglong2 s0 = sK[t][0], s1 = sK[t][1], s2_ = sK[t][2],
                             s3 = sK[t][3], s4 = sK[t][4], s5 = sK[t][5],
                             s6 = sK[t][6];
            const u64 P1d = s0.x, P1n = s0.y, P1n2 = s1.x, P2a = s1.y;
            const u64 P2b = s2_.x, P2b2 = s2_.y, Cd = s3.x, Cn = s3.y;
            const u64 Cn2 = s4.x, Qd = s4.y, Qn = s5.x, Qn2 = s5.y;
            const u64 CK  = s6.x;

            // ---- phase A: local-only work (no shifted Fp/Fm needed) ----
            u64 zf = fma2(A2,  Zb, fma2(A1,  Zf, CF0));
            u64 zb = fma2(B2p, Zf, fma2(B1p, Zb, CB0));
            u64 zfS  = swp(zf);
            u64 cdzf = mul2(Cd, zf);
            u64 t1   = fma2(Cn,  zfS, cdzf);   // C*zf        (for Fpn)
            u64 t2   = fma2(Cn2, zfS, cdzf);   // conj(C)*zf  (for Fmn)
            u64 ckzf = mul2(CK, zf);           // ck*zf       (for Zfn)

            // ---- phase B: shifted-state work (short tree after exchange) ----
            u64 FpS = swp(Fp), FmS = swp(Fm);
            u64 Fpn = fma2(P1n,  FpS, fma2(P1d, Fp, fma2(P2b,  FmS, fma2(P2a, Fm, t1))));
            u64 Fmn = fma2(P1n2, FmS, fma2(P1d, Fm, fma2(P2b2, FpS, fma2(P2a, Fp, t2))));
            u64 Zfn = fma2(Qd, add2(Fp, Fm), fma2(Qn, FpS, fma2(Qn2, FmS, ckzf)));

            // ---- global stores (real parts, rotated columns = post-shift) ----
            p0[0] = is127 ? 0.f : lo32(Fpn);
            p1[0] = is0   ? 0.f : lo32(Fmn);
            p2[0] = lo32(Zfn);
            p5[0] = lo32(zb);
            p0 += NS; p1 += NS; p2 += NS; p5 += NS;

            // ---- exchange: halo arrays make boundaries branch/select-free ----
            exFp[b][i + 1] = Fpn;
            exFm[b][i]     = Fmn;
            __syncthreads();
            Fp = exFp[b][i];        // == 0 for i==0 (permanent halo)
            Fm = exFm[b][i + 1];    // == 0 for i==127 (permanent halo)
            Zf = Zfn;
            Zb = zb;
            b ^= 1;
        }
    }
}

extern "C" void kernel_launch(void* const* d_in, const int* in_sizes, int n_in,
                              void* d_out, int out_size)
{
    (void)in_sizes; (void)n_in;
    const float* flip  = (const float*)d_in[0];
    const float* phase = (const float*)d_in[1];
    const float* T1f   = (const float*)d_in[2];
    const float* T2f   = (const float*)d_in[3];
    const float* T1b   = (const float*)d_in[4];
    const float* T2b   = (const float*)d_in[5];
    const float* kf    = (const float*)d_in[6];
    const float* kb    = (const float*)d_in[7];
    const float* TR    = (const float*)d_in[8];
    // d_in[9] = TE (unused by the reference math)
    const float* B0    = (const float*)d_in[10];
    const float* B1    = (const float*)d_in[11];
    const float* wf    = (const float*)d_in[12];
    const float* wb    = (const float*)d_in[13];

    // Zero-fill pools 3,4 (identically zero), clamped to buffer size.
    long long z_lo = (long long)3 * PPOOL;
    long long z_hi = (long long)5 * PPOOL;
    if (z_hi > (long long)out_size) z_hi = out_size;
    if (z_hi > z_lo) {
        int n = (int)(z_hi - z_lo);
        epg_zero1<<<(n + 255) / 256, 256>>>((float*)d_out + z_lo, n);
    }

    epg_mt_kernel<<<1, 128>>>(flip, phase, T1f, T2f, T1b, T2b, kf, kb,
                              TR, B0, B1, wf, wb, (float*)d_out);
}

// round 15
// speedup vs baseline: 1.6018x; 1.5083x over previous
#include <cuda_runtime.h>
#include <math.h>

#define NP 4096
#define NS 128
#define CH 256
#define PPOOL (NP * NS)   // elements per pool (float32 reals)

// Zero-fill for pools 3,4 (Fp_b, Fm_b identically zero).
__global__ void epg_zero1(float* __restrict__ p, int n)
{
    int k = blockIdx.x * blockDim.x + threadIdx.x;
    if (k < n) p[k] = 0.f;
}

__global__ void __launch_bounds__(128, 1)
epg_mt_kernel(const float* __restrict__ flip, const float* __restrict__ phase,
              const float* __restrict__ pT1f, const float* __restrict__ pT2f,
              const float* __restrict__ pT1b, const float* __restrict__ pT2b,
              const float* __restrict__ pkf,  const float* __restrict__ pkb,
              const float* __restrict__ pTR,  const float* __restrict__ pB0,
              const float* __restrict__ pB1,  const float* __restrict__ pwf,
              const float* __restrict__ pwb,
              float* __restrict__ out)
{
    // Per-pulse constants: k0=(P1x,P1y,P2x,P2y), k1=(Cx,Cy,Qx,Qy), ck
    __shared__ float4 sk0[CH];
    __shared__ float4 sk1[CH];
    __shared__ float  sck[CH];
    // Interleaved exchange with PERMANENT zero halos.
    // Slot S[b][i+1] read by thread i as one LDS.128:
    //   .xy = new Fp_i = Fpn_{i-1}   (written by thread i-1 into S[(i-1)+2])
    //   .zw = new Fm_i = Fmn_{i+1}   (written by thread i+1 into S[(i+1)])
    // Halos: S[b][1].xy == 0 (no thread -1), S[b][NS].zw == 0 (no thread NS).
    __shared__ float4 S[2][NS + 2];

    const int i = threadIdx.x;                 // state 0..127

    // ---- scalar params / derived constants ----
    const float TR  = pTR[0];
    const float T1f = pT1f[0], T2f = pT2f[0];
    const float T1b = pT1b[0];
    const float kf  = pkf[0],  kb  = pkb[0];
    const float B0  = pB0[0],  B1  = pB1[0];
    const float wf  = pwf[0],  wb  = pwb[0];

    const float E1f = expf(-TR / T1f);
    const float E2f = expf(-TR / T2f);
    const float E1b = expf(-TR / T1b);
    const float scale = TR / 1000.0f;

    const float a1 = E1f - kf * scale;
    const float a2 = kb * scale;
    const float Cf = (1.0f - E1f) * wf;
    const float b1 = E1b - kb * scale;
    const float b2 = kf * scale;
    const float Cb = (1.0f - E1b) * wb;

    const float phi = 2.0f * 3.14159265358979323846f * B0 * TR / 1000.0f;
    float rs, rc;
    sincosf(phi, &rs, &rc);
    const float Rx = E2f * rc;     // R = E2f * e^{i phi} (relax+rot fused)
    const float Ry = E2f * rs;

    // ---- initial carry ----
    float Fpx = 0.f, Fpy = 0.f, Fmx = 0.f, Fmy = 0.f;
    float Zfx = (i == 0) ? wf : 0.f, Zfy = 0.f;
    float Zbx = (i == 0) ? wb : 0.f, Zby = 0.f;

    const bool is0   = (i == 0);
    const bool is127 = (i == NS - 1);
    const int  iprev = (i + NS - 1) & (NS - 1);
    const int  inext = (i + 1) & (NS - 1);

    // Zero halo slots once (never rewritten: no thread writes these offsets).
    if (i == 0) {
        S[0][1].x = 0.f;  S[0][1].y = 0.f;  S[1][1].x = 0.f;  S[1][1].y = 0.f;
        S[0][NS].z = 0.f; S[0][NS].w = 0.f; S[1][NS].z = 0.f; S[1][NS].w = 0.f;
    }

    // Rotated-column output pointers (post-shift layout, stores off-chain).
    float* p0 = out + inext;                 // pool0: Re(Fp) post-shift
    float* p1 = out + PPOOL + iprev;         // pool1: Re(Fm) post-shift
    float* p2 = out + 2 * PPOOL + i;         // pool2: Re(Zf)
    float* p5 = out + 5 * PPOOL + i;         // pool5: Re(Zb)

    int b = 0;

    for (int base = 0; base < NP; base += CH) {
        __syncthreads();   // previous chunk's const readers done
        // ---- cooperative precompute of per-pulse constants ----
        for (int j = i; j < CH; j += 128) {
            float fa = flip[base + j] * B1;
            float ph = phase[base + j];
            float s, c;
            sincosf(0.5f * fa, &s, &c);
            float c2 = c * c, s2 = s * s, cs = c * s;
            float sb, cb;
            sincosf(ph, &sb, &cb);
            float Ax = s2 * (cb * cb - sb * sb);   // A = s2 e^{2i ph}
            float Ay = s2 * (2.f * sb * cb);
            float Cx = -cs * sb;                   // C = i cs e^{i ph}
            float Cy =  cs * cb;
            // P1 = c2*R ; P2 = A*R ; Q = conj(C)*R
            sk0[j] = make_float4(c2 * Rx, c2 * Ry,
                                 Ax * Rx - Ay * Ry, Ax * Ry + Ay * Rx);
            sk1[j] = make_float4(Cx, Cy,
                                 Cx * Rx + Cy * Ry, Cx * Ry - Cy * Rx);
            sck[j] = c2 - s2;
        }
        __syncthreads();

        #pragma unroll 4
        for (int t = 0; t < CH; ++t) {
            const float4 k0 = sk0[t];           // broadcast LDS (1 phase)
            const float4 k1 = sk1[t];
            const float  ck = sck[t];
            const float P1x = k0.x, P1y = k0.y, P2x = k0.z, P2y = k0.w;
            const float Cx  = k1.x, Cy  = k1.y, Qx  = k1.z, Qy  = k1.w;

            // ---- phase A: Z-only work (independent of exchanged F) ----
            float zfx = fmaf(a2, Zbx, fmaf(a1, Zfx, Cf));
            float zfy = fmaf(a1, Zfy, a2 * Zby);
            float zbx = fmaf(b2, Zfx, fmaf(b1, Zbx, Cb));
            float zby = fmaf(b1, Zby, b2 * Zfy);
            // C*zf and conj(C)*zf (share products)
            float cxzx = Cx * zfx, cyzy = Cy * zfy;
            float cxzy = Cx * zfy, cyzx = Cy * zfx;
            float t1x = cxzx - cyzy, t1y = cxzy + cyzx;   // C*zf
            float t2x = cxzx + cyzy, t2y = cxzy - cyzx;   // conj(C)*zf
            float ckzx = ck * zfx,  ckzy = ck * zfy;

            // ---- phase B: short trees on exchanged Fp/Fm ----
            // Fpn = P1*Fp + P2*conj(Fm) + C*zf
            float Fpn_x = fmaf(P1x, Fpx, fmaf(-P1y, Fpy,
                          fmaf(P2x, Fmx, fmaf( P2y, Fmy, t1x))));
            float Fpn_y = fmaf(P1x, Fpy, fmaf( P1y, Fpx,
                          fmaf(-P2x, Fmy, fmaf( P2y, Fmx, t1y))));
            // Fmn = conj(P2)*conj(Fp) + conj(P1)*Fm + conj(C)*zf
            float Fmn_x = fmaf( P2x, Fpx, fmaf(-P2y, Fpy,
                          fmaf( P1x, Fmx, fmaf( P1y, Fmy, t2x))));
            float Fmn_y = fmaf(-P2x, Fpy, fmaf(-P2y, Fpx,
                          fmaf( P1x, Fmy, fmaf(-P1y, Fmx, t2y))));
            // Zfn = Q*Fp + conj(Q)*Fm + ck*zf  (factored)
            float Zfn_x = fmaf(Qx, Fpx + Fmx, fmaf(Qy, Fmy - Fpy, ckzx));
            float Zfn_y = fmaf(Qx, Fpy + Fmy, fmaf(Qy, Fpx - Fmx, ckzy));

            // ---- global stores (real parts, rotated columns = post-shift) ----
            p0[0] = is127 ? 0.f : Fpn_x;
            p1[0] = is0   ? 0.f : Fmn_x;
            p2[0] = Zfn_x;
            p5[0] = zbx;
            p0 += NS; p1 += NS; p2 += NS; p5 += NS;

            // ---- exchange: 2x STS.64 + BAR + 1x LDS.128 ----
            S[b][i + 2].x = Fpn_x;  S[b][i + 2].y = Fpn_y;   // -> thread i+1
            S[b][i].z     = Fmn_x;  S[b][i].w     = Fmn_y;   // -> thread i-1
            __syncthreads();
            float4 ex = S[b][i + 1];
            Fpx = ex.x; Fpy = ex.y;       // zero halo handles i==0
            Fmx = ex.z; Fmy = ex.w;       // zero halo handles i==127
            Zfx = Zfn_x; Zfy = Zfn_y;
            Zbx = zbx;   Zby = zby;
            b ^= 1;
        }
    }
}

extern "C" void kernel_launch(void* const* d_in, const int* in_sizes, int n_in,
                              void* d_out, int out_size)
{
    (void)in_sizes; (void)n_in;
    const float* flip  = (const float*)d_in[0];
    const float* phase = (const float*)d_in[1];
    const float* T1f   = (const float*)d_in[2];
    const float* T2f   = (const float*)d_in[3];
    const float* T1b   = (const float*)d_in[4];
    const float* T2b   = (const float*)d_in[5];
    const float* kf    = (const float*)d_in[6];
    const float* kb    = (const float*)d_in[7];
    const float* TR    = (const float*)d_in[8];
    // d_in[9] = TE (unused by the reference math)
    const float* B0    = (const float*)d_in[10];
    const float* B1    = (const float*)d_in[11];
    const float* wf    = (const float*)d_in[12];
    const float* wb    = (const float*)d_in[13];

    // Zero-fill pools 3,4 (identically zero), clamped to buffer size.
    long long z_lo = (long long)3 * PPOOL;
    long long z_hi = (long long)5 * PPOOL;
    if (z_hi > (long long)out_size) z_hi = out_size;
    if (z_hi > z_lo) {
        int n = (int)(z_hi - z_lo);
        epg_zero1<<<(n + 255) / 256, 256>>>((float*)d_out + z_lo, n);
    }

    epg_mt_kernel<<<1, 128>>>(flip, phase, T1f, T2f, T1b, T2b, kf, kb,
                              TR, B0, B1, wf, wb, (float*)d_out);
}

// round 17
// speedup vs baseline: 1.6658x; 1.0400x over previous
#include <cuda_runtime.h>
#include <math.h>

#define NP 4096
#define NS 128
#define CH 256
#define PPOOL (NP * NS)   // elements per pool (float32 reals)

// Zero-fill for pools 3,4 (Fp_b, Fm_b identically zero).
__global__ void epg_zero1(float* __restrict__ p, int n)
{
    int k = blockIdx.x * blockDim.x + threadIdx.x;
    if (k < n) p[k] = 0.f;
}

__global__ void __launch_bounds__(128, 1)
epg_mt_kernel(const float* __restrict__ flip, const float* __restrict__ phase,
              const float* __restrict__ pT1f, const float* __restrict__ pT2f,
              const float* __restrict__ pT1b, const float* __restrict__ pT2b,
              const float* __restrict__ pkf,  const float* __restrict__ pkb,
              const float* __restrict__ pTR,  const float* __restrict__ pB0,
              const float* __restrict__ pB1,  const float* __restrict__ pwf,
              const float* __restrict__ pwb,
              float* __restrict__ out)
{
    // Per-pulse constants: k0=(P1x,P1y,P2x,P2y), k1=(Cx,Cy,Qx,Qy), ck
    // One extra (zeroed) slot so the in-loop phase-A prefetch for t+1==CH is
    // harmless (its C/ck-dependent products are recomputed at next chunk top).
    __shared__ float4 sk0[CH + 1];
    __shared__ float4 sk1[CH + 1];
    __shared__ float  sck[CH + 1];
    // Interleaved exchange with PERMANENT zero halos.
    //   S[b][i+1].xy = new Fp_i (written by thread i-1 into S[(i-1)+2])
    //   S[b][i+1].zw = new Fm_i (written by thread i+1 into S[(i+1)])
    __shared__ float4 S[2][NS + 2];

    const int i = threadIdx.x;                 // state 0..127

    // ---- scalar params / derived constants ----
    const float TR  = pTR[0];
    const float T1f = pT1f[0], T2f = pT2f[0];
    const float T1b = pT1b[0];
    const float kf  = pkf[0],  kb  = pkb[0];
    const float B0  = pB0[0],  B1  = pB1[0];
    const float wf  = pwf[0],  wb  = pwb[0];

    const float E1f = expf(-TR / T1f);
    const float E2f = expf(-TR / T2f);
    const float E1b = expf(-TR / T1b);
    const float scale = TR / 1000.0f;

    const float a1 = E1f - kf * scale;
    const float a2 = kb * scale;
    const float Cf = (1.0f - E1f) * wf;
    const float b1 = E1b - kb * scale;
    const float b2 = kf * scale;
    const float Cb = (1.0f - E1b) * wb;

    const float phi = 2.0f * 3.14159265358979323846f * B0 * TR / 1000.0f;
    float rs, rc;
    sincosf(phi, &rs, &rc);
    const float Rx = E2f * rc;     // R = E2f * e^{i phi} (relax+rot fused)
    const float Ry = E2f * rs;

    const bool is0   = (i == 0);
    const bool is127 = (i == NS - 1);
    const int  iprev = (i + NS - 1) & (NS - 1);
    const int  inext = (i + 1) & (NS - 1);

    // Zero halo slots + spare const slot once.
    if (i == 0) {
        S[0][1].x = 0.f;  S[0][1].y = 0.f;  S[1][1].x = 0.f;  S[1][1].y = 0.f;
        S[0][NS].z = 0.f; S[0][NS].w = 0.f; S[1][NS].z = 0.f; S[1][NS].w = 0.f;
        sk0[CH] = make_float4(0.f, 0.f, 0.f, 0.f);
        sk1[CH] = make_float4(0.f, 0.f, 0.f, 0.f);
        sck[CH] = 0.f;
    }

    // ---- initial carry + phase-A (invariant part) for pulse 0 ----
    float Fpx = 0.f, Fpy = 0.f, Fmx = 0.f, Fmy = 0.f;
    {
        // phase A for pulse 0 from initial (Zf, Zb)
    }
    const float Zf0 = (i == 0) ? wf : 0.f;
    const float Zb0 = (i == 0) ? wb : 0.f;
    float zfx = fmaf(a2, Zb0, fmaf(a1, Zf0, Cf));
    float zfy = 0.f;
    float zbx = fmaf(b2, Zf0, fmaf(b1, Zb0, Cb));
    float zby = 0.f;
    // pulse-const-dependent phase-A products (t1,t2,ckz) + phase-B consts are
    // (re)computed at each chunk top from zf / sk*[0].
    float t1x = 0.f, t1y = 0.f, t2x = 0.f, t2y = 0.f, ckzx = 0.f, ckzy = 0.f;
    float P1x = 0.f, P1y = 0.f, P2x = 0.f, P2y = 0.f, Qx = 0.f, Qy = 0.f;

    // Rotated-column output pointers (post-shift layout, stores off-chain).
    float* p0 = out + inext;                 // pool0: Re(Fp) post-shift
    float* p1 = out + PPOOL + iprev;         // pool1: Re(Fm) post-shift
    float* p2 = out + 2 * PPOOL + i;         // pool2: Re(Zf)
    float* p5 = out + 5 * PPOOL + i;         // pool5: Re(Zb)

    int b = 0;

    for (int base = 0; base < NP; base += CH) {
        __syncthreads();   // previous chunk's const readers done
        // ---- cooperative precompute of per-pulse constants ----
        for (int j = i; j < CH; j += 128) {
            float fa = flip[base + j] * B1;
            float ph = phase[base + j];
            float s, c;
            sincosf(0.5f * fa, &s, &c);
            float c2 = c * c, s2 = s * s, cs = c * s;
            float sb, cb;
            sincosf(ph, &sb, &cb);
            float Ax = s2 * (cb * cb - sb * sb);   // A = s2 e^{2i ph}
            float Ay = s2 * (2.f * sb * cb);
            float Cx = -cs * sb;                   // C = i cs e^{i ph}
            float Cy =  cs * cb;
            sk0[j] = make_float4(c2 * Rx, c2 * Ry,
                                 Ax * Rx - Ay * Ry, Ax * Ry + Ay * Rx);
            sk1[j] = make_float4(Cx, Cy,
                                 Cx * Rx + Cy * Ry, Cx * Ry - Cy * Rx);
            sck[j] = c2 - s2;
        }
        __syncthreads();

        // ---- chunk top: finish phase A for this chunk's first pulse ----
        {
            const float4 k0c = sk0[0];
            const float4 k1c = sk1[0];
            const float  ckc = sck[0];
            float cxzx = k1c.x * zfx, cyzy = k1c.y * zfy;
            float cxzy = k1c.x * zfy, cyzx = k1c.y * zfx;
            t1x = cxzx - cyzy; t1y = cxzy + cyzx;   // C*zf
            t2x = cxzx + cyzy; t2y = cxzy - cyzx;   // conj(C)*zf
            ckzx = ckc * zfx;  ckzy = ckc * zfy;
            P1x = k0c.x; P1y = k0c.y; P2x = k0c.z; P2y = k0c.w;
            Qx  = k1c.z; Qy  = k1c.w;
        }

        #pragma unroll 4
        for (int t = 0; t < CH; ++t) {
            // ---- phase B: trees on exchanged Fp/Fm (post-barrier work) ----
            // Fpn = P1*Fp + P2*conj(Fm) + C*zf
            float Fpn_x = fmaf(P1x, Fpx, fmaf(-P1y, Fpy,
                          fmaf(P2x, Fmx, fmaf( P2y, Fmy, t1x))));
            float Fpn_y = fmaf(P1x, Fpy, fmaf( P1y, Fpx,
                          fmaf(-P2x, Fmy, fmaf( P2y, Fmx, t1y))));
            // Fmn = conj(P2)*conj(Fp) + conj(P1)*Fm + conj(C)*zf
            float Fmn_x = fmaf( P2x, Fpx, fmaf(-P2y, Fpy,
                          fmaf( P1x, Fmx, fmaf( P1y, Fmy, t2x))));
            float Fmn_y = fmaf(-P2x, Fpy, fmaf(-P2y, Fpx,
                          fmaf( P1x, Fmy, fmaf(-P1y, Fmx, t2y))));
            // Zfn = Q*Fp + conj(Q)*Fm + ck*zf  (factored)
            float Zfn_x = fmaf(Qx, Fpx + Fmx, fmaf(Qy, Fmy - Fpy, ckzx));
            float Zfn_y = fmaf(Qx, Fpy + Fmy, fmaf(Qy, Fpx - Fmx, ckzy));

            // ---- exchange stores first (release our contribution early) ----
            S[b][i + 2].x = Fpn_x;  S[b][i + 2].y = Fpn_y;   // -> thread i+1
            S[b][i].z     = Fmn_x;  S[b][i].w     = Fmn_y;   // -> thread i-1

            // ---- global stores (real parts, rotated columns = post-shift) ----
            p0[0] = is127 ? 0.f : Fpn_x;
            p1[0] = is0   ? 0.f : Fmn_x;
            p2[0] = Zfn_x;
            p5[0] = zbx;
            p0 += NS; p1 += NS; p2 += NS; p5 += NS;

            // ---- prefetch consts + phase A for pulse t+1 (pre-barrier!) ----
            const float4 nk0 = sk0[t + 1];
            const float4 nk1 = sk1[t + 1];
            const float  nck = sck[t + 1];
            // z relaxation/exchange (loop-invariant coeffs -> valid even when
            // t+1 == CH; the const-dependent products get redone at chunk top)
            float nzfx = fmaf(a2, zbx, fmaf(a1, Zfn_x, Cf));
            float nzfy = fmaf(a1, Zfn_y, a2 * zby);
            float nzbx = fmaf(b2, Zfn_x, fmaf(b1, zbx, Cb));
            float nzby = fmaf(b1, zby, b2 * Zfn_y);
            float cxzx = nk1.x * nzfx, cyzy = nk1.y * nzfy;
            float cxzy = nk1.x * nzfy, cyzx = nk1.y * nzfx;

            // rotate carries (unroll renaming -> no physical MOVs)
            zfx = nzfx; zfy = nzfy; zbx = nzbx; zby = nzby;
            t1x = cxzx - cyzy; t1y = cxzy + cyzx;
            t2x = cxzx + cyzy; t2y = cxzy - cyzx;
            ckzx = nck * nzfx; ckzy = nck * nzfy;
            P1x = nk0.x; P1y = nk0.y; P2x = nk0.z; P2y = nk0.w;
            Qx = nk1.z;  Qy = nk1.w;

            // ---- barrier + exchange load (only LDS + phase B after this) ----
            __syncthreads();
            float4 ex = S[b][i + 1];
            Fpx = ex.x; Fpy = ex.y;       // zero halo handles i==0
            Fmx = ex.z; Fmy = ex.w;       // zero halo handles i==127
            b ^= 1;
        }
    }
}

extern "C" void kernel_launch(void* const* d_in, const int* in_sizes, int n_in,
                              void* d_out, int out_size)
{
    (void)in_sizes; (void)n_in;
    const float* flip  = (const float*)d_in[0];
    const float* phase = (const float*)d_in[1];
    const float* T1f   = (const float*)d_in[2];
    const float* T2f   = (const float*)d_in[3];
    const float* T1b   = (const float*)d_in[4];
    const float* T2b   = (const float*)d_in[5];
    const float* kf    = (const float*)d_in[6];
    const float* kb    = (const float*)d_in[7];
    const float* TR    = (const float*)d_in[8];
    // d_in[9] = TE (unused by the reference math)
    const float* B0    = (const float*)d_in[10];
    const float* B1    = (const float*)d_in[11];
    const float* wf    = (const float*)d_in[12];
    const float* wb    = (const float*)d_in[13];

    // Zero-fill pools 3,4 (identically zero), clamped to buffer size.
    long long z_lo = (long long)3 * PPOOL;
    long long z_hi = (long long)5 * PPOOL;
    if (z_hi > (long long)out_size) z_hi = out_size;
    if (z_hi > z_lo) {
        int n = (int)(z_hi - z_lo);
        epg_zero1<<<(n + 255) / 256, 256>>>((float*)d_out + z_lo, n);
    }

    epg_mt_kernel<<<1, 128>>>(flip, phase, T1f, T2f, T1b, T2b, kf, kb,
                              TR, B0, B1, wf, wb, (float*)d_out);
}